// round 5
// baseline (speedup 1.0000x reference)
#include <cuda_runtime.h>
#include <math.h>

// Problem constants
#define Bz 64
#define Tt 512
#define Dd 1024
#define Hh 1024
#define G4 4096   // 4*H

// ---------------------------------------------------------------------------
// Scratch (static __device__ globals; no allocation allowed)
// ---------------------------------------------------------------------------
__device__ float g_xz[(size_t)Tt * Bz * G4];   // 512 MB  (time-major: [t][b][4H])
__device__ float g_hs0[(size_t)Tt * Bz * Hh];  // 128 MB  (layer0 hs, time-major [t][b][H])
__device__ float g_h[2][Bz * Hh];              // ping-pong h
__device__ float g_c[Bz * Hh];                 // cell state

// software grid barrier state (returns to 0 after each launch: even #flips)
__device__ unsigned g_bar_count = 0;
__device__ unsigned g_bar_sense = 0;

// ---------------------------------------------------------------------------
// Grid-wide sync for a fully-resident grid (sense-reversing barrier).
// All cross-block data uses __stcg/__ldcg (L2 coherence point), and the
// pre-arrival __threadfence makes this launch-replay safe.
// ---------------------------------------------------------------------------
__device__ __forceinline__ void grid_sync(unsigned& sense, unsigned nblocks) {
    __threadfence();
    __syncthreads();
    if (threadIdx.x == 0) {
        const unsigned s = sense ^ 1u;
        sense = s;
        if (atomicAdd(&g_bar_count, 1u) == nblocks - 1u) {
            atomicExch(&g_bar_count, 0u);
            __threadfence();
            atomicExch(&g_bar_sense, s);
        } else {
            while (atomicAdd(&g_bar_sense, 0u) != s) { __nanosleep(64); }
        }
    }
    __syncthreads();
}

// ---------------------------------------------------------------------------
// SGEMM for xz = A @ W + bias, A is (32768 x 1024), W (1024 x 4096).
// Row m = t*B + b.  layer0: A[m][k] = x[b][t][k]  (x is (B,T,D))
//                   layer1: A[m][k] = g_hs0[m][k]
// 128x128 block tile, BK=16, 256 threads, 8x8 per-thread, double buffered.
// ---------------------------------------------------------------------------
__global__ void __launch_bounds__(256) gemm_xz_kernel(
    const float* __restrict__ Aext, const float* __restrict__ W,
    const float* __restrict__ bias, int layer0)
{
    __shared__ float As[2][16][132];
    __shared__ float Bs[2][16][128];

    const int tid = threadIdx.x;
    const int bm = blockIdx.y * 128;
    const int bn = blockIdx.x * 128;

    const int aRow = tid >> 2;           // 0..63
    const int aCol = (tid & 3) << 2;     // 0,4,8,12
    const float* aptr0;
    const float* aptr1;
    {
        int m0 = bm + aRow;
        int m1 = m0 + 64;
        if (layer0) {
            aptr0 = Aext + ((size_t)(m0 & 63) * Tt + (m0 >> 6)) * Dd;
            aptr1 = Aext + ((size_t)(m1 & 63) * Tt + (m1 >> 6)) * Dd;
        } else {
            aptr0 = g_hs0 + (size_t)m0 * Hh;
            aptr1 = g_hs0 + (size_t)m1 * Hh;
        }
    }
    const int bRow = tid >> 5;           // 0..7
    const int bCol = (tid & 31) << 2;
    const float* wptr = W + (size_t)bRow * G4 + bn + bCol;

    float4 ra0 = *(const float4*)(aptr0 + aCol);
    float4 ra1 = *(const float4*)(aptr1 + aCol);
    float4 rb0 = *(const float4*)(wptr);
    float4 rb1 = *(const float4*)(wptr + (size_t)8 * G4);

    As[0][aCol + 0][aRow] = ra0.x; As[0][aCol + 1][aRow] = ra0.y;
    As[0][aCol + 2][aRow] = ra0.z; As[0][aCol + 3][aRow] = ra0.w;
    As[0][aCol + 0][aRow + 64] = ra1.x; As[0][aCol + 1][aRow + 64] = ra1.y;
    As[0][aCol + 2][aRow + 64] = ra1.z; As[0][aCol + 3][aRow + 64] = ra1.w;
    *(float4*)&Bs[0][bRow][bCol] = rb0;
    *(float4*)&Bs[0][bRow + 8][bCol] = rb1;
    __syncthreads();

    float acc[8][8];
#pragma unroll
    for (int i = 0; i < 8; i++)
#pragma unroll
        for (int j = 0; j < 8; j++) acc[i][j] = 0.0f;

    const int ty = tid >> 4;   // 0..15
    const int tx = tid & 15;   // 0..15

    int buf = 0;
    for (int k0 = 16;; k0 += 16) {
        const bool more = (k0 < 1024);
        if (more) {
            ra0 = *(const float4*)(aptr0 + k0 + aCol);
            ra1 = *(const float4*)(aptr1 + k0 + aCol);
            rb0 = *(const float4*)(wptr + (size_t)k0 * G4);
            rb1 = *(const float4*)(wptr + (size_t)(k0 + 8) * G4);
        }
#pragma unroll
        for (int kk = 0; kk < 16; kk++) {
            float ar[8], br[8];
            *(float4*)&ar[0] = *(const float4*)&As[buf][kk][ty * 8];
            *(float4*)&ar[4] = *(const float4*)&As[buf][kk][ty * 8 + 4];
            *(float4*)&br[0] = *(const float4*)&Bs[buf][kk][tx * 8];
            *(float4*)&br[4] = *(const float4*)&Bs[buf][kk][tx * 8 + 4];
#pragma unroll
            for (int i = 0; i < 8; i++)
#pragma unroll
                for (int j = 0; j < 8; j++) acc[i][j] += ar[i] * br[j];
        }
        if (!more) break;
        const int nb = buf ^ 1;
        As[nb][aCol + 0][aRow] = ra0.x; As[nb][aCol + 1][aRow] = ra0.y;
        As[nb][aCol + 2][aRow] = ra0.z; As[nb][aCol + 3][aRow] = ra0.w;
        As[nb][aCol + 0][aRow + 64] = ra1.x; As[nb][aCol + 1][aRow + 64] = ra1.y;
        As[nb][aCol + 2][aRow + 64] = ra1.z; As[nb][aCol + 3][aRow + 64] = ra1.w;
        *(float4*)&Bs[nb][bRow][bCol] = rb0;
        *(float4*)&Bs[nb][bRow + 8][bCol] = rb1;
        __syncthreads();
        buf = nb;
    }

    float bb[8];
    *(float4*)&bb[0] = *(const float4*)(bias + bn + tx * 8);
    *(float4*)&bb[4] = *(const float4*)(bias + bn + tx * 8 + 4);
#pragma unroll
    for (int i = 0; i < 8; i++) {
        const int m = bm + ty * 8 + i;
        float* crow = g_xz + (size_t)m * G4 + bn + tx * 8;
        float4 o0, o1;
        o0.x = acc[i][0] + bb[0]; o0.y = acc[i][1] + bb[1];
        o0.z = acc[i][2] + bb[2]; o0.w = acc[i][3] + bb[3];
        o1.x = acc[i][4] + bb[4]; o1.y = acc[i][5] + bb[5];
        o1.z = acc[i][6] + bb[6]; o1.w = acc[i][7] + bb[7];
        *(float4*)(crow) = o0;
        *(float4*)(crow + 4) = o1;
    }
}

// ---------------------------------------------------------------------------
// Persistent LSTM scan: ONE kernel does all 512 timesteps for one layer.
// grid = 128 blocks (8 hidden-cols each -> 32 gate-cols), 128 threads.
// All blocks co-resident (128 <= 148 SMs); software grid barrier between steps.
// Cross-block h traffic uses __stcg/__ldcg (L2-coherent).
// ---------------------------------------------------------------------------
__global__ void __launch_bounds__(128) lstm_scan_kernel(
    const float* __restrict__ U, const int* __restrict__ lengths,
    float* __restrict__ out_base, int layer)
{
    __shared__ float hsm[32][64];   // [k][b]
    __shared__ float usm[32][36];   // [k][c]  (padded)
    __shared__ float zsm[64][32];   // [b][c]

    const int tid = threadIdx.x;
    const int j0 = blockIdx.x * 8;
    const unsigned nblocks = gridDim.x;
    unsigned sense = 0;

    // zero h (both buffers) and c, distributed over the whole grid
    {
        const int base = blockIdx.x * 128 + tid;   // 0..16383
#pragma unroll
        for (int q = 0; q < 4; q++) {
            const int i = base + q * 16384;
            g_h[0][i] = 0.0f;
            g_h[1][i] = 0.0f;
            g_c[i] = 0.0f;
        }
    }
    grid_sync(sense, nblocks);   // sync #1

    const int tr = tid >> 3;     // 0..15 (rows 4tr..4tr+3)
    const int tc = tid & 7;      // 0..7  (cols 4tc..4tc+3)
    const int hb = tid >> 1;            // 0..63
    const int hkq = (tid & 1) << 4;     // 0 or 16
    const int uk = tid >> 2;            // 0..31
    const int ug = tid & 3;             // groups ug, ug+4

    // per-thread (b, j) assignments for the gate stage
    int len_b[4];
#pragma unroll
    for (int r = 0; r < 4; r++) {
        const int p = r * 128 + tid;
        len_b[r] = lengths[p >> 3];
    }

    for (int t = 0; t < Tt; t++) {
        const float* __restrict__ hin = g_h[t & 1];
        float* __restrict__ hout = g_h[(t & 1) ^ 1];
        const float* __restrict__ xz = g_xz + (size_t)t * (Bz * G4);

        float acc[4][4];
#pragma unroll
        for (int i = 0; i < 4; i++)
#pragma unroll
            for (int j = 0; j < 4; j++) acc[i][j] = 0.0f;

        for (int k0 = 0; k0 < Hh; k0 += 32) {
            // load h chunk, transposed to [k][b]  (L2-coherent loads)
#pragma unroll
            for (int q = 0; q < 4; q++) {
                float4 v = __ldcg((const float4*)(hin + (size_t)hb * Hh + k0 + hkq + q * 4));
                hsm[hkq + q * 4 + 0][hb] = v.x;
                hsm[hkq + q * 4 + 1][hb] = v.y;
                hsm[hkq + q * 4 + 2][hb] = v.z;
                hsm[hkq + q * 4 + 3][hb] = v.w;
            }
            // load U chunk
#pragma unroll
            for (int q = 0; q < 2; q++) {
                const int g = ug + q * 4;           // 0..7
                const int gate = g >> 1;
                const int cj = (g & 1) * 4;
                const float* up = U + (size_t)(k0 + uk) * G4 + gate * Hh + j0 + cj;
                *(float4*)&usm[uk][g * 4] = *(const float4*)up;
            }
            __syncthreads();
#pragma unroll
            for (int k = 0; k < 32; k++) {
                float4 hv = *(const float4*)&hsm[k][tr * 4];
                float4 uv = *(const float4*)&usm[k][tc * 4];
                float hvv[4] = {hv.x, hv.y, hv.z, hv.w};
                float uvv[4] = {uv.x, uv.y, uv.z, uv.w};
#pragma unroll
                for (int i = 0; i < 4; i++)
#pragma unroll
                    for (int j = 0; j < 4; j++) acc[i][j] += hvv[i] * uvv[j];
            }
            __syncthreads();
        }

        // stage z = acc + xz into smem
#pragma unroll
        for (int i = 0; i < 4; i++) {
            const int b = tr * 4 + i;
#pragma unroll
            for (int j = 0; j < 4; j++) {
                const int cc = tc * 4 + j;
                const int gate = cc >> 3;
                const int jj = cc & 7;
                zsm[b][cc] = acc[i][j] + xz[(size_t)b * G4 + gate * Hh + j0 + jj];
            }
        }
        __syncthreads();

        // gate math + state update: 512 (b,j) pairs, 4 per thread
#pragma unroll
        for (int r = 0; r < 4; r++) {
            const int p = r * 128 + tid;
            const int b = p >> 3;
            const int jj = p & 7;
            const int j = j0 + jj;

            const float zi = zsm[b][jj];
            const float zf = zsm[b][8 + jj];
            const float zg = zsm[b][16 + jj];
            const float zo = zsm[b][24 + jj];

            const float ig = 1.0f / (1.0f + __expf(-zi));
            const float fg = 1.0f / (1.0f + __expf(-zf));
            const float gg = tanhf(zg);
            const float og = 1.0f / (1.0f + __expf(-zo));

            const size_t hidx = (size_t)b * Hh + j;
            const float cold = g_c[hidx];
            const float cn = fg * cold + ig * gg;
            const float hn = og * tanhf(cn);

            const bool msk = (t < len_b[r]);
            const float h2 = msk ? hn : __ldcg(hin + hidx);
            const float c2 = msk ? cn : cold;

            __stcg(hout + hidx, h2);
            g_c[hidx] = c2;
            if (layer == 0) {
                g_hs0[(size_t)t * (Bz * Hh) + hidx] = h2;
            } else {
                out_base[(size_t)b * ((size_t)Tt * Hh) + (size_t)t * Hh + j] = h2;
            }
        }

        if (t < Tt - 1) grid_sync(sense, nblocks);   // syncs #2..#512 (even total)
    }
}

// ---------------------------------------------------------------------------
// Copy final h, c into output tail
// ---------------------------------------------------------------------------
__global__ void copy_hc_kernel(float* __restrict__ out_tail) {
    int i = blockIdx.x * 256 + threadIdx.x;
    if (i < Bz * Hh) {
        out_tail[i] = g_h[0][i];              // T=512 even -> final h in buf 0
        out_tail[Bz * Hh + i] = g_c[i];
    }
}

// ---------------------------------------------------------------------------
// Launch: 5 graph nodes total (was 1029 -> driver graph-upload buffer leak)
// ---------------------------------------------------------------------------
extern "C" void kernel_launch(void* const* d_in, const int* in_sizes, int n_in,
                              void* d_out, int out_size) {
    (void)in_sizes; (void)n_in; (void)out_size;
    const float* x  = (const float*)d_in[0];
    const int* lens = (const int*)d_in[1];
    const float* W0 = (const float*)d_in[2];
    const float* U0 = (const float*)d_in[3];
    const float* b0 = (const float*)d_in[4];
    const float* W1 = (const float*)d_in[5];
    const float* U1 = (const float*)d_in[6];
    const float* b1 = (const float*)d_in[7];
    float* out = (float*)d_out;

    const dim3 ggrid(G4 / 128, (Tt * Bz) / 128);   // 32 x 256
    const int hcBlocks = (Bz * Hh + 255) / 256;

    // Layer 0
    gemm_xz_kernel<<<ggrid, 256>>>(x, W0, b0, 1);
    lstm_scan_kernel<<<128, 128>>>(U0, lens, nullptr, 0);

    // Layer 1
    gemm_xz_kernel<<<ggrid, 256>>>(nullptr, W1, b1, 0);
    lstm_scan_kernel<<<128, 128>>>(U1, lens, out, 1);

    // Final h, c
    copy_hc_kernel<<<hcBlocks, 256>>>(out + (size_t)Bz * Tt * Hh);
}